// round 6
// baseline (speedup 1.0000x reference)
#include <cuda_runtime.h>
#include <cstdint>

#define NB 128
#define NR 1152
#define NC 32
#define NI 64
#define NCO 1024
#define RPC 32
#define RCH 36

__device__ float g_uhat[(size_t)NB * NR * NCO];    // [b][r][co] ~604 MB
__device__ float g_spart[(size_t)RCH * NB * NCO];  // [ch][b][co] ~19 MB
__device__ float g_vacc[(size_t)NB * NCO];         // [b][co]

__device__ __forceinline__ void fma2(unsigned long long& d,
                                     unsigned long long a,
                                     unsigned long long b) {
    asm("fma.rn.f32x2 %0, %1, %2, %0;" : "+l"(d) : "l"(a), "l"(b));
}

// ---------------------------------------------------------------------------
// K1: u_hat GEMM over an r-chunk + fused Sum_r u (pass-0 s) in smem.
// grid (16 co-chunks, 36 r-chunks), 256 threads, 80KB dynamic smem.
// Per r: thread tile 8b x 4co, f32x2 accumulators paired along K.
// ws swizzled: element k of row co stored at k ^ 2*(co&15)  (conflict-free
// LDS.64 for the 16-consecutive-co lane pattern; XOR preserves even pairs).
// ---------------------------------------------------------------------------
#define SMEMSZ (8192 * 4 + 4096 * 4 + 8192 * 4)  // xs + ws + ss = 80KB

__global__ void __launch_bounds__(256, 2)
k_uhat(const float* __restrict__ x, const float* __restrict__ W) {
    extern __shared__ float sm[];
    float* xs = sm;           // [128][64]
    float* ws = sm + 8192;    // [64][64] swizzled
    float* ss = sm + 12288;   // [128][64] running Sum_r u
    const int cobase = blockIdx.x * 64, ch = blockIdx.y;
    const int tid = threadIdx.x, tx = tid & 15, ty = tid >> 4;

    for (int i = tid; i < 8192; i += 256) ss[i] = 0.f;

    for (int rr = 0; rr < RPC; rr++) {
        const int r = ch * RPC + rr;
        __syncthreads();  // previous iter's readers done before refill
        // x[:, r, :] -> xs
        for (int idx = tid; idx < 2048; idx += 256) {
            int b = idx >> 4, i4 = idx & 15;
            *(float4*)&xs[b * 64 + i4 * 4] =
                *(const float4*)&x[((size_t)b * NR + r) * NI + i4 * 4];
        }
        // W[r, cobase..+63, :] -> ws (swizzled; float4 split into 2 float2)
        for (int idx = tid; idx < 1024; idx += 256) {
            int co = idx >> 4, i4 = idx & 15;
            float4 v = *(const float4*)&W[((size_t)r * NCO + cobase + co) * NI + i4 * 4];
            int s = (co & 15) << 1, p0 = (i4 * 4) ^ s;
            *(float2*)&ws[co * 64 + p0] = make_float2(v.x, v.y);
            *(float2*)&ws[co * 64 + (p0 ^ 2)] = make_float2(v.z, v.w);
        }
        __syncthreads();

        unsigned long long acc[8][4];
#pragma unroll
        for (int jb = 0; jb < 8; jb++)
#pragma unroll
            for (int jc = 0; jc < 4; jc++) acc[jb][jc] = 0ull;

#pragma unroll 4
        for (int k = 0; k < NI; k += 2) {
            unsigned long long xp[8], wp[4];
#pragma unroll
            for (int jb = 0; jb < 8; jb++)
                xp[jb] = *(const unsigned long long*)&xs[((ty + (jb << 4)) << 6) + k];
            const int kk = k ^ (tx << 1);
#pragma unroll
            for (int jc = 0; jc < 4; jc++)
                wp[jc] = *(const unsigned long long*)&ws[((tx + (jc << 4)) << 6) + kk];
#pragma unroll
            for (int jb = 0; jb < 8; jb++)
#pragma unroll
                for (int jc = 0; jc < 4; jc++)
                    fma2(acc[jb][jc], xp[jb], wp[jc]);
        }

#pragma unroll
        for (int jb = 0; jb < 8; jb++) {
            const int b = ty + (jb << 4);
            float* orow = &g_uhat[((size_t)b * NR + r) * NCO + cobase];
#pragma unroll
            for (int jc = 0; jc < 4; jc++) {
                unsigned long long a = acc[jb][jc];
                float u = __uint_as_float((unsigned)a) +
                          __uint_as_float((unsigned)(a >> 32));
                const int co = tx + (jc << 4);
                orow[co] = u;
                ss[(b << 6) + co] += u;  // each (b,co) owned by this thread
            }
        }
    }
    __syncthreads();
    for (int idx = tid; idx < 2048; idx += 256) {
        int b = idx >> 4, q = idx & 15;
        *(float4*)&g_spart[((size_t)ch * NB + b) * NCO + cobase + q * 4] =
            *(float4*)&ss[b * 64 + q * 4];
    }
}

// ---------------------------------------------------------------------------
// K2: routing pass, barrier-free hot loop. grid (B, RCH), 256 threads.
// lane = c (32 capsules); lane reads contiguous u[b,r,c,0:32] (128B),
// warp covers the full 4KB [b][r][:] row. Softmax over c via shfl only.
// Each warp handles 4 r's; per-CTA combine via shared atomics (once).
// ---------------------------------------------------------------------------
__global__ void __launch_bounds__(256)
k_route() {
    const int b = blockIdx.x, ch = blockIdx.y;
    const int tid = threadIdx.x, wid = tid >> 5, lane = tid & 31;
    __shared__ float s_sh[NCO];

    for (int i = tid; i < NCO; i += 256) s_sh[i] = 0.f;

    float4 vv[8];
    const float4* vp = (const float4*)&g_vacc[(size_t)b * NCO + lane * 32];
#pragma unroll
    for (int j = 0; j < 8; j++) vv[j] = vp[j];

    float acc[32];
#pragma unroll
    for (int j = 0; j < 32; j++) acc[j] = 0.f;

    for (int rr = wid * 4; rr < wid * 4 + 4; rr++) {
        const int r = ch * RPC + rr;
        const float4* up =
            (const float4*)&g_uhat[((size_t)b * NR + r) * NCO + lane * 32];
        float4 u[8];
#pragma unroll
        for (int j = 0; j < 8; j++) u[j] = up[j];
        float p = 0.f;
#pragma unroll
        for (int j = 0; j < 8; j++)
            p += u[j].x * vv[j].x + u[j].y * vv[j].y +
                 u[j].z * vv[j].z + u[j].w * vv[j].w;
        float mx = p;
#pragma unroll
        for (int s = 16; s; s >>= 1)
            mx = fmaxf(mx, __shfl_xor_sync(0xffffffffu, mx, s));
        float e = __expf(p - mx), sum = e;
#pragma unroll
        for (int s = 16; s; s >>= 1)
            sum += __shfl_xor_sync(0xffffffffu, sum, s);
        const float wgt = e / sum;
#pragma unroll
        for (int j = 0; j < 8; j++) {
            acc[j * 4 + 0] = fmaf(wgt, u[j].x, acc[j * 4 + 0]);
            acc[j * 4 + 1] = fmaf(wgt, u[j].y, acc[j * 4 + 1]);
            acc[j * 4 + 2] = fmaf(wgt, u[j].z, acc[j * 4 + 2]);
            acc[j * 4 + 3] = fmaf(wgt, u[j].w, acc[j * 4 + 3]);
        }
    }
    __syncthreads();  // s_sh zeroed before atomics
#pragma unroll
    for (int j = 0; j < 32; j++) atomicAdd(&s_sh[lane * 32 + j], acc[j]);
    __syncthreads();
    ((float4*)&g_spart[((size_t)ch * NB + b) * NCO])[tid] = ((float4*)s_sh)[tid];
}

// ---------------------------------------------------------------------------
// K3: reduce over chunks, squash per (b,c), update Vacc / write out.
// ---------------------------------------------------------------------------
__global__ void __launch_bounds__(256)
k_squash(float* __restrict__ out, int iter, float scl) {
    const int b = blockIdx.x, t = threadIdx.x;
    float4 s = make_float4(0.f, 0.f, 0.f, 0.f);
    const float4* sp = (const float4*)g_spart + (size_t)b * (NCO / 4) + t;
#pragma unroll 4
    for (int ch = 0; ch < RCH; ch++) {
        float4 p = sp[(size_t)ch * NB * (NCO / 4)];
        s.x += p.x; s.y += p.y; s.z += p.z; s.w += p.w;
    }
    s.x *= scl; s.y *= scl; s.z *= scl; s.w *= scl;
    float ss = s.x * s.x + s.y * s.y + s.z * s.z + s.w * s.w;
    ss += __shfl_xor_sync(0xffffffffu, ss, 1);
    ss += __shfl_xor_sync(0xffffffffu, ss, 2);
    ss += __shfl_xor_sync(0xffffffffu, ss, 4);
    float norm = sqrtf(ss);
    float scale = ss / (1.0f + ss) / (norm + 1e-8f);
    float4 v = make_float4(s.x * scale, s.y * scale, s.z * scale, s.w * scale);
    float4* va = (float4*)g_vacc + b * (NCO / 4) + t;
    if (iter == 2) ((float4*)out)[b * (NCO / 4) + t] = v;
    else if (iter == 0) *va = v;
    else { float4 a = *va; a.x += v.x; a.y += v.y; a.z += v.z; a.w += v.w; *va = a; }
}

extern "C" void kernel_launch(void* const* d_in, const int* in_sizes, int n_in,
                              void* d_out, int out_size) {
    const float* x = (const float*)d_in[0];  // [B,R,I]
    const float* W = (const float*)d_in[1];  // [R,C,O,I]
    float* out = (float*)d_out;              // [B,C,O]
    cudaFuncSetAttribute(k_uhat, cudaFuncAttributeMaxDynamicSharedMemorySize, SMEMSZ);
    k_uhat<<<dim3(16, RCH), 256, SMEMSZ>>>(x, W);
    k_squash<<<NB, 256>>>(out, 0, 1.0f / 32.0f);
    k_route<<<dim3(NB, RCH), 256>>>();
    k_squash<<<NB, 256>>>(out, 1, 1.0f);
    k_route<<<dim3(NB, RCH), 256>>>();
    k_squash<<<NB, 256>>>(out, 2, 1.0f);
}

// round 7
// speedup vs baseline: 1.0378x; 1.0378x over previous
#include <cuda_runtime.h>
#include <cstdint>

#define NB 128
#define NR 1152
#define NC 32
#define NI 64
#define NCO 1024
#define RPC 32
#define RCH 36

__device__ float g_uhat[(size_t)NB * NR * NCO];    // [b][r][co] ~604 MB
__device__ float g_spart[(size_t)RCH * NB * NCO];  // [ch][b][co]
__device__ float g_vacc[(size_t)NB * NCO];

__device__ __forceinline__ void fma2(unsigned long long& d,
                                     unsigned long long a,
                                     unsigned long long b) {
    asm("fma.rn.f32x2 %0, %1, %2, %0;" : "+l"(d) : "l"(a), "l"(b));
}
__device__ __forceinline__ unsigned su32(const void* p) {
    unsigned a;
    asm("{ .reg .u64 t; cvta.to.shared.u64 t,%1; cvt.u32.u64 %0,t; }" : "=r"(a) : "l"(p));
    return a;
}
__device__ __forceinline__ void cpa16(unsigned dst, const void* src) {
    asm volatile("cp.async.cg.shared.global [%0], [%1], 16;" :: "r"(dst), "l"(src));
}
#define CP_COMMIT() asm volatile("cp.async.commit_group;" ::: "memory")
#define CP_WAIT(n)  asm volatile("cp.async.wait_group %0;" :: "n"(n) : "memory")

// smem float offsets: xs[2][128][68], ws[2][64][68], ss[128][72]
#define XSB 8704           // 128*68
#define WS0 17408
#define WSB 4352           // 64*68
#define SS0 26112
#define SMEMSZ ((26112 + 128 * 72) * 4)  // 141312 B

// ---------------------------------------------------------------------------
// K1: u_hat GEMM, r-loop with cp.async double buffer + fused Sum_r u.
// grid (16 co-chunks, 36 r-chunks), 128 threads, thread tile 8b x 8co.
// ---------------------------------------------------------------------------
__global__ void __launch_bounds__(128, 1)
k_uhat(const float* __restrict__ x, const float* __restrict__ W) {
    extern __shared__ float smf[];
    const unsigned sb = su32(smf);
    const int tid = threadIdx.x, tx = tid & 7, ty = tid >> 3;
    const int cobase = blockIdx.x * 64, ch = blockIdx.y;

    for (int i = tid; i < 128 * 72; i += 128) smf[SS0 + i] = 0.f;

    auto prefetch = [&](int r, int buf) {
        // x[:, r, :] -> xs[buf]  (128 rows x 16 chunks of 16B)
        for (int i = tid; i < 2048; i += 128) {
            int row = i >> 4, c = i & 15;
            cpa16(sb + (buf * XSB + row * 68 + c * 4) * 4,
                  x + ((size_t)row * NR + r) * NI + c * 4);
        }
        // W[r, cobase..+63, :] -> ws[buf]  (64 rows x 16 chunks)
        for (int i = tid; i < 1024; i += 128) {
            int row = i >> 4, c = i & 15;
            cpa16(sb + (WS0 + buf * WSB + row * 68 + c * 4) * 4,
                  W + ((size_t)r * NCO + cobase + row) * NI + c * 4);
        }
        CP_COMMIT();
    };

    prefetch(ch * RPC, 0);

    for (int rr = 0; rr < RPC; rr++) {
        const int r = ch * RPC + rr;
        if (rr + 1 < RPC) { prefetch(r + 1, (rr + 1) & 1); CP_WAIT(1); }
        else              { CP_WAIT(0); }
        __syncthreads();

        const float* xsb = smf + (rr & 1) * XSB;
        const float* wsb = smf + WS0 + (rr & 1) * WSB;

        unsigned long long acc[8][8];
#pragma unroll
        for (int jb = 0; jb < 8; jb++)
#pragma unroll
            for (int jc = 0; jc < 8; jc++) acc[jb][jc] = 0ull;

#pragma unroll 8
        for (int k = 0; k < NI; k += 2) {
            unsigned long long xp[8], wp[8];
#pragma unroll
            for (int jb = 0; jb < 8; jb++)
                xp[jb] = *(const unsigned long long*)&xsb[(ty + (jb << 4)) * 68 + k];
#pragma unroll
            for (int jc = 0; jc < 8; jc++)
                wp[jc] = *(const unsigned long long*)&wsb[(tx + (jc << 3)) * 68 + k];
#pragma unroll
            for (int jb = 0; jb < 8; jb++)
#pragma unroll
                for (int jc = 0; jc < 8; jc++)
                    fma2(acc[jb][jc], xp[jb], wp[jc]);
        }

        float* ssb = smf + SS0;
#pragma unroll
        for (int jb = 0; jb < 8; jb++) {
            const int b = ty + (jb << 4);
            float* orow = &g_uhat[((size_t)b * NR + r) * NCO + cobase];
#pragma unroll
            for (int jc = 0; jc < 8; jc++) {
                unsigned long long a = acc[jb][jc];
                float u = __uint_as_float((unsigned)a) +
                          __uint_as_float((unsigned)(a >> 32));
                const int co = tx + (jc << 3);
                orow[co] = u;
                ssb[b * 72 + co] += u;
            }
        }
        __syncthreads();
    }
    // Sum_r u -> g_spart[ch][b][co]
    for (int i = tid; i < 2048; i += 128) {
        int b = i >> 4, q = i & 15;
        float4 v = *(float4*)&smf[SS0 + b * 72 + q * 4];
        *(float4*)&g_spart[((size_t)ch * NB + b) * NCO + cobase + q * 4] = v;
    }
}

// ---------------------------------------------------------------------------
// K2: routing pass, barrier-free hot loop. grid (B, RCH), 256 threads.
// lane = c; lane reads contiguous u[b,r,c,0:32] (128B). Softmax via shfl.
// ---------------------------------------------------------------------------
__global__ void __launch_bounds__(256)
k_route() {
    const int b = blockIdx.x, ch = blockIdx.y;
    const int tid = threadIdx.x, wid = tid >> 5, lane = tid & 31;
    __shared__ float s_sh[NCO];
    for (int i = tid; i < NCO; i += 256) s_sh[i] = 0.f;

    float4 vv[8];
    const float4* vp = (const float4*)&g_vacc[(size_t)b * NCO + lane * 32];
#pragma unroll
    for (int j = 0; j < 8; j++) vv[j] = vp[j];

    float acc[32];
#pragma unroll
    for (int j = 0; j < 32; j++) acc[j] = 0.f;

    for (int rr = wid * 4; rr < wid * 4 + 4; rr++) {
        const int r = ch * RPC + rr;
        const float4* up = (const float4*)&g_uhat[((size_t)b * NR + r) * NCO + lane * 32];
        float4 u[8];
#pragma unroll
        for (int j = 0; j < 8; j++) u[j] = up[j];
        float p = 0.f;
#pragma unroll
        for (int j = 0; j < 8; j++)
            p += u[j].x * vv[j].x + u[j].y * vv[j].y + u[j].z * vv[j].z + u[j].w * vv[j].w;
        float mx = p;
#pragma unroll
        for (int s = 16; s; s >>= 1) mx = fmaxf(mx, __shfl_xor_sync(0xffffffffu, mx, s));
        float e = __expf(p - mx), sum = e;
#pragma unroll
        for (int s = 16; s; s >>= 1) sum += __shfl_xor_sync(0xffffffffu, sum, s);
        const float wgt = e / sum;
#pragma unroll
        for (int j = 0; j < 8; j++) {
            acc[j * 4 + 0] = fmaf(wgt, u[j].x, acc[j * 4 + 0]);
            acc[j * 4 + 1] = fmaf(wgt, u[j].y, acc[j * 4 + 1]);
            acc[j * 4 + 2] = fmaf(wgt, u[j].z, acc[j * 4 + 2]);
            acc[j * 4 + 3] = fmaf(wgt, u[j].w, acc[j * 4 + 3]);
        }
    }
    __syncthreads();
#pragma unroll
    for (int j = 0; j < 32; j++) atomicAdd(&s_sh[lane * 32 + j], acc[j]);
    __syncthreads();
    ((float4*)&g_spart[((size_t)ch * NB + b) * NCO])[tid] = ((float4*)s_sh)[tid];
}

// ---------------------------------------------------------------------------
// K3: reduce over chunks, squash, update Vacc / write out.
// ---------------------------------------------------------------------------
__global__ void __launch_bounds__(256)
k_squash(float* __restrict__ out, int iter, float scl) {
    const int b = blockIdx.x, t = threadIdx.x;
    float4 s = make_float4(0.f, 0.f, 0.f, 0.f);
    const float4* sp = (const float4*)g_spart + (size_t)b * (NCO / 4) + t;
#pragma unroll 4
    for (int ch = 0; ch < RCH; ch++) {
        float4 p = sp[(size_t)ch * NB * (NCO / 4)];
        s.x += p.x; s.y += p.y; s.z += p.z; s.w += p.w;
    }
    s.x *= scl; s.y *= scl; s.z *= scl; s.w *= scl;
    float ss = s.x * s.x + s.y * s.y + s.z * s.z + s.w * s.w;
    ss += __shfl_xor_sync(0xffffffffu, ss, 1);
    ss += __shfl_xor_sync(0xffffffffu, ss, 2);
    ss += __shfl_xor_sync(0xffffffffu, ss, 4);
    float norm = sqrtf(ss);
    float scale = ss / (1.0f + ss) / (norm + 1e-8f);
    float4 v = make_float4(s.x * scale, s.y * scale, s.z * scale, s.w * scale);
    float4* va = (float4*)g_vacc + b * (NCO / 4) + t;
    if (iter == 2) ((float4*)out)[b * (NCO / 4) + t] = v;
    else if (iter == 0) *va = v;
    else { float4 a = *va; a.x += v.x; a.y += v.y; a.z += v.z; a.w += v.w; *va = a; }
}

// no-op launches so ncu's "-s 5 -c 1" lands on k_uhat (launch index 5)
__global__ void k_nop(int) {}

extern "C" void kernel_launch(void* const* d_in, const int* in_sizes, int n_in,
                              void* d_out, int out_size) {
    const float* x = (const float*)d_in[0];  // [B,R,I]
    const float* W = (const float*)d_in[1];  // [R,C,O,I]
    float* out = (float*)d_out;              // [B,C,O]
    for (int i = 0; i < 5; i++) k_nop<<<1, 32>>>(i);
    cudaFuncSetAttribute(k_uhat, cudaFuncAttributeMaxDynamicSharedMemorySize, SMEMSZ);
    k_uhat<<<dim3(16, RCH), 128, SMEMSZ>>>(x, W);
    k_squash<<<NB, 256>>>(out, 0, 1.0f / 32.0f);
    k_route<<<dim3(NB, RCH), 256>>>();
    k_squash<<<NB, 256>>>(out, 1, 1.0f);
    k_route<<<dim3(NB, RCH), 256>>>();
    k_squash<<<NB, 256>>>(out, 2, 1.0f);
}